// round 16
// baseline (speedup 1.0000x reference)
#include <cuda_runtime.h>
#include <cuda_bf16.h>
#include <cstdint>

#define B_    32
#define CIN_  12
#define LEN_  1024
#define TT_   64
#define C1_   64
#define C2_   128

// Scratch (device globals; no runtime allocation)
__device__ float         g_xT[TT_ * B_ * CIN_ * LEN_];          // [t][b][cin][l]
__device__ unsigned char g_s1T[(size_t)TT_ * B_ * LEN_ * C1_];  // [t][b][l][c1] spikes
__device__ uint4         g_Apk[7168];      // packed s8 w2 frags [c2h][plane][mi][chunk][lane]
__device__ uint4         g_Alo4[2 * 1792]; // lo plane frag-vectors [c2h][koff][c1w][wy][g]
__device__ float         g_pool[B_ * C2_];

typedef unsigned long long u64;

// ---- packed f32x2 helpers (conv1) ----
__device__ __forceinline__ u64 pack2(float lo, float hi) {
    u64 r;
    asm("mov.b64 %0, {%1, %2};" : "=l"(r) : "f"(lo), "f"(hi));
    return r;
}
__device__ __forceinline__ void unpack2(u64 v, float& lo, float& hi) {
    asm("mov.b64 {%0, %1}, %2;" : "=f"(lo), "=f"(hi) : "l"(v));
}
__device__ __forceinline__ void ffma2(u64& d, u64 a, u64 b) {
    asm("fma.rn.f32x2 %0, %1, %2, %0;" : "+l"(d) : "l"(a), "l"(b));
}
__device__ __forceinline__ void dp4a(int& acc, unsigned a, unsigned b) {
    asm("dp4a.s32.s32 %0, %1, %2, %0;" : "+r"(acc) : "r"(a), "r"(b));
}

// ---- warp MMA: m16n8k32 s8.s8.s32 ----
#define IMMA16832(D, A, B0, B1)                                              \
    asm volatile(                                                            \
        "mma.sync.aligned.m16n8k32.row.col.s32.s8.s8.s32 "                   \
        "{%0,%1,%2,%3}, {%4,%5,%6,%7}, {%8,%9}, {%0,%1,%2,%3};"              \
        : "+r"((D)[0]), "+r"((D)[1]), "+r"((D)[2]), "+r"((D)[3])             \
        : "r"((A).x), "r"((A).y), "r"((A).z), "r"((A).w), "r"(B0), "r"(B1))

// ============================================================================
// Kernel A: quantize + pack w2 (exact 2-plane split at 2^15) + zero g_pool.
// ============================================================================
__global__ void __launch_bounds__(256) w2prep_kernel(const float* __restrict__ w2) {
    int idx = blockIdx.x * 256 + threadIdx.x;
    if (idx < B_ * C2_) g_pool[idx] = 0.f;
    if (idx >= 7168) return;

    auto lo_of = [&](int m, int c1, int koff) -> int {
        float w = w2[m * 448 + c1 * 7 + koff];
        int q = __float2int_rn(w * 32768.f);
        int hi = (q + 128) >> 8;
        return q - (hi << 8);
    };

    // ---- IMMA fragment packing (hi plane used by conv2f) ----
    {
        int lane = idx & 31;
        int r    = idx >> 5;
        int chunk = r % 14;
        int r2    = r / 14;
        int mi    = r2 & 3;
        int plane = (r2 >> 2) & 1;
        int c2h   = r2 >> 3;
        int g = lane >> 2, c = lane & 3;
        int h = chunk & 1, koff = chunk >> 1;
        int m0 = c2h * 64 + mi * 16;
        int c1b = 32 * h + 4 * c;

        auto pk4 = [&](int m, int c1s) -> unsigned {
            unsigned rr = 0;
#pragma unroll
            for (int j = 0; j < 4; ++j) {
                float w = w2[m * 448 + (c1s + j) * 7 + koff];
                int q = __float2int_rn(w * 32768.f);
                int hi = (q + 128) >> 8;
                int lo = q - (hi << 8);
                int val = plane ? lo : hi;
                rr |= ((unsigned)(val & 0xFF)) << (8 * j);
            }
            return rr;
        };
        uint4 out;
        out.x = pk4(m0 + g,     c1b);
        out.y = pk4(m0 + g + 8, c1b);
        out.z = pk4(m0 + g,     c1b + 16);
        out.w = pk4(m0 + g + 8, c1b + 16);
        g_Apk[idx] = out;
    }

    // ---- dp4a lo fragment vectors (full plane, c1 0..63) ----
    if (idx < 3584) {
        int g    = idx & 7;
        int wy   = (idx >> 3) & 1;
        int c1w  = (idx >> 4) & 15;
        int kk   = idx >> 8;            // c2h*7 + koff
        int koff = kk % 7;
        int c2h  = kk / 7;
        unsigned w4[4];
#pragma unroll
        for (int j = 0; j < 4; ++j) {
            int m = c2h * 64 + wy * 32 + g + 8 * j;
            unsigned rr = 0;
#pragma unroll
            for (int jj = 0; jj < 4; ++jj) {
                int lo = lo_of(m, 4 * c1w + jj, koff);
                rr |= ((unsigned)(lo & 0xFF)) << (8 * jj);
            }
            w4[j] = rr;
        }
        g_Alo4[idx] = make_uint4(w4[0], w4[1], w4[2], w4[3]);
    }
}

// ============================================================================
// Kernel B: transpose x [b][cin][l][t] -> g_xT [t][b][cin][l]
// ============================================================================
__global__ void __launch_bounds__(256) transpose_kernel(const float* __restrict__ x) {
    __shared__ float tile[32][33];
    const int bc = blockIdx.z;
    const int t0 = blockIdx.x * 32;
    const int l0 = blockIdx.y * 32;
    const int tx = threadIdx.x;
    const int ty = threadIdx.y;
    const float* xb = x + (size_t)bc * LEN_ * TT_;
#pragma unroll
    for (int j = 0; j < 4; ++j)
        tile[ty + j * 8][tx] = xb[(size_t)(l0 + ty + j * 8) * TT_ + t0 + tx];
    __syncthreads();
#pragma unroll
    for (int j = 0; j < 4; ++j)
        g_xT[((size_t)(t0 + ty + j * 8) * (B_ * CIN_) + bc) * LEN_ + l0 + tx] =
            tile[tx][ty + j * 8];
}

// ============================================================================
// Kernel C: conv1 (12->64, K=7) + LIF1 (tau=1 stateless), FFMA2, standalone.
// Emits spikes TRANSPOSED: g_s1T[t][b][l][c1] via smem tile.
// ============================================================================
__global__ void __launch_bounds__(256) conv1_kernel(const float* __restrict__ w1,
                                                    const float* __restrict__ b1) {
    __shared__ float ws[84 * 68];
    __shared__ float xs[12][136];
    __shared__ unsigned char st[128 * 80];   // [l_local][c1], pitch 80

    const int tid = threadIdx.x;
    const int l0  = blockIdx.x * 128;
    const int b   = blockIdx.y;
    const int t   = blockIdx.z;

    for (int i = tid; i < C1_ * 84; i += 256) {
        int c1 = i / 84, r = i % 84;
        ws[r * 68 + c1] = w1[i];
    }
    const float* xb = g_xT + ((size_t)(t * B_ + b) * CIN_) * LEN_;
    for (int i = tid; i < 12 * 134; i += 256) {
        int cin = i / 134, j = i % 134;
        int l = l0 - 3 + j;
        xs[cin][j] = (l >= 0 && l < LEN_) ? xb[cin * LEN_ + l] : 0.f;
    }
    __syncthreads();

    const int c1g = tid >> 5;
    const int lg  = tid & 31;

    u64 acc[8][2];
#pragma unroll
    for (int c = 0; c < 8; ++c) { acc[c][0] = 0ull; acc[c][1] = 0ull; }

#pragma unroll 1
    for (int cin = 0; cin < 12; ++cin) {
        const float* sp = &xs[cin][lg * 4];
        float4 a0 = *reinterpret_cast<const float4*>(sp);
        float4 a1 = *reinterpret_cast<const float4*>(sp + 4);
        float4 a2 = *reinterpret_cast<const float4*>(sp + 8);
        float sv[12] = {a0.x, a0.y, a0.z, a0.w, a1.x, a1.y, a1.z, a1.w,
                        a2.x, a2.y, a2.z, a2.w};
        u64 pv[9];
#pragma unroll
        for (int j = 0; j < 9; ++j) pv[j] = pack2(sv[j], sv[j + 1]);
#pragma unroll
        for (int k = 0; k < 7; ++k) {
            const float* wp = &ws[(cin * 7 + k) * 68 + c1g * 8];
            float4 w0 = *reinterpret_cast<const float4*>(wp);
            float4 w1v = *reinterpret_cast<const float4*>(wp + 4);
            float wr[8] = {w0.x, w0.y, w0.z, w0.w, w1v.x, w1v.y, w1v.z, w1v.w};
#pragma unroll
            for (int c = 0; c < 8; ++c) {
                u64 wb = pack2(wr[c], wr[c]);
                ffma2(acc[c][0], pv[k], wb);
                ffma2(acc[c][1], pv[k + 2], wb);
            }
        }
    }

    // spikes for 8 c1 x 4 l -> byte matrix, write rows into st
    unsigned char sp8[4][8];
#pragma unroll
    for (int c = 0; c < 8; ++c) {
        float bb = b1[c1g * 8 + c];
        float v0, v1, v2, v3;
        unpack2(acc[c][0], v0, v1);
        unpack2(acc[c][1], v2, v3);
        sp8[0][c] = (2.f * (v0 + bb) >= 0.5f) ? 1 : 0;
        sp8[1][c] = (2.f * (v1 + bb) >= 0.5f) ? 1 : 0;
        sp8[2][c] = (2.f * (v2 + bb) >= 0.5f) ? 1 : 0;
        sp8[3][c] = (2.f * (v3 + bb) >= 0.5f) ? 1 : 0;
    }
#pragma unroll
    for (int i = 0; i < 4; ++i) {
        u64 v = 0;
#pragma unroll
        for (int c = 0; c < 8; ++c) v |= (u64)sp8[i][c] << (8 * c);
        *reinterpret_cast<u64*>(st + (lg * 4 + i) * 80 + c1g * 8) = v;
    }
    __syncthreads();

    // coalesced write-out: 128 rows x 64 B
    unsigned char* dst = g_s1T + ((size_t)(t * B_ + b) * LEN_ + l0) * 64;
#pragma unroll
    for (int j = 0; j < 2; ++j) {
        int idx = tid * 2 + j;
        int row = idx >> 2, q = idx & 3;
        uint4 val = *reinterpret_cast<const uint4*>(st + row * 80 + q * 16);
        *reinterpret_cast<uint4*>(dst + row * 64 + q * 16) = val;
    }
}

// ============================================================================
// Kernel D: slim conv2 with BLOCK-PARITY ANTI-PHASE scheduling:
// even blockIdx.x: per-t (IMMA phase -> dp4a phase)
// odd  blockIdx.x: per-t (dp4a phase -> IMMA phase)
// Co-resident blocks (adjacent bids) thus feed DIFFERENT pipes at any instant,
// keeping the SM-shared tensor unit busy through the other block's dp4a burst.
// Arithmetic identical to r14/r15 (integer-exact).
// ============================================================================
#define SPT_PITCH 80
#define SPT_ROWS  70
#define OFF_SA   0                       //  28672 B  IMMA A frags (hi plane)
#define OFF_ALO  28672                   //  28672 B  dp4a lo frag vectors
#define OFF_SPT0 (OFF_ALO + 28672)       //   5760 B
#define OFF_SPT1 (OFF_SPT0 + 5760)       //   5760 B
#define SMEM_SZ  (OFF_SPT1 + 5760)       //  68864 B

extern __shared__ char fsm[];

__global__ void __launch_bounds__(256, 2)
conv2f_kernel(const float* __restrict__ b2) {
    const int tid  = threadIdx.x;
    const int lane = tid & 31;
    const int wid  = tid >> 5;
    const int wy = wid >> 2;        // 0..1  M group of 32
    const int wx = wid & 3;         // 0..3  N group of 16
    const int g  = lane >> 2;
    const int c  = lane & 3;
    const int lt  = blockIdx.x;     // 0..15
    const int c2h = blockIdx.y;     // 0..1
    const int b   = blockIdx.z;     // 0..31
    const int l0  = lt * 64;
    const bool swapord = (blockIdx.x & 1) != 0;

    uint4* sA    = reinterpret_cast<uint4*>(fsm + OFF_SA);
    uint4* sAlo4 = reinterpret_cast<uint4*>(fsm + OFF_ALO);
    char*  spt[2] = {fsm + OFF_SPT0, fsm + OFF_SPT1};

    // ---- one-time staging ----
    {
#pragma unroll 7
        for (int i = tid; i < 1792; i += 256) {
            int mi = i / 448, rem = i % 448;
            sA[i] = g_Apk[(c2h * 8 + mi) * 448 + rem];
        }
        const uint4* gL = g_Alo4 + c2h * 1792;
#pragma unroll 7
        for (int i = tid; i < 1792; i += 256) sAlo4[i] = gL[i];
    }

    // per-t spike tile copy (70 rows x 64 B)
    auto construct = [&](int t, char* buf) {
        const uint4* gs = reinterpret_cast<const uint4*>(
            g_s1T + ((size_t)(t * B_ + b) * LEN_) * 64);
#pragma unroll 2
        for (int i = tid; i < SPT_ROWS * 4; i += 256) {
            int j = i >> 2, q = i & 3;
            int l = l0 - 3 + j;
            uint4 val = make_uint4(0, 0, 0, 0);
            if (l >= 0 && l < LEN_) val = gs[l * 4 + q];
            *reinterpret_cast<uint4*>(buf + j * SPT_PITCH + q * 16) = val;
        }
    };

    construct(0, spt[0]);
    __syncthreads();

    float bb[2][2];
#pragma unroll
    for (int mt = 0; mt < 2; ++mt)
#pragma unroll
        for (int hf = 0; hf < 2; ++hf)
            bb[mt][hf] = 2.f * b2[c2h * 64 + wy * 32 + mt * 16 + g + hf * 8];

    float v[2][2][4];
#pragma unroll
    for (int mt = 0; mt < 2; ++mt)
#pragma unroll
        for (int nt = 0; nt < 2; ++nt)
#pragma unroll
            for (int e = 0; e < 4; ++e) v[mt][nt][e] = 0.f;
    float accs[2][2] = {{0.f, 0.f}, {0.f, 0.f}};

    const float SCALE = 6.103515625e-05f;   // 2^-14
    const float INV_TAU = 1.0f / 0.9f;

    // hoisted invariant bases
    const uint4* sA_l    = sA + lane;
    const uint4* a4base  = sAlo4 + wy * 8 + g;
    const int    browOff = (wx * 16 + g) * SPT_PITCH + c * 4;
    const int    rowbOff = (wx * 16 + 2 * c) * SPT_PITCH;

#pragma unroll 1
    for (int t = 0; t < TT_; ++t) {
        const char* curB = spt[t & 1];

        // issue next tile's loads first: LDG latency hides under compute
        if (t + 1 < TT_) construct(t + 1, spt[(t + 1) & 1]);

        const char* brow_b = curB + browOff;
        const char* rowb_b = curB + rowbOff;

        int dh[2][2][4], ds[2][2][4];
#pragma unroll
        for (int mt = 0; mt < 2; ++mt)
#pragma unroll
            for (int nt = 0; nt < 2; ++nt)
#pragma unroll
                for (int e = 0; e < 4; ++e) { dh[mt][nt][e] = 0; ds[mt][nt][e] = 0; }

        // ---- phase bodies (compact loops to keep I$ small) ----
        auto tensor_phase = [&]() {
#pragma unroll 1
            for (int koff = 0; koff < 7; ++koff) {
                const int ch0 = koff * 2, ch1 = ch0 + 1;
                uint4 ah0[2], ah1[2];
#pragma unroll
                for (int mt = 0; mt < 2; ++mt) {
                    int mi = wy * 2 + mt;
                    ah0[mt] = sA_l[(mi * 14 + ch0) * 32];
                    ah1[mt] = sA_l[(mi * 14 + ch1) * 32];
                }
                const char* brow = brow_b + koff * SPT_PITCH;
                unsigned b00[2], b01[2], b10[2], b11[2];
#pragma unroll
                for (int nt = 0; nt < 2; ++nt) {
                    const char* p = brow + nt * 8 * SPT_PITCH;
                    b00[nt] = *reinterpret_cast<const unsigned*>(p);
                    b01[nt] = *reinterpret_cast<const unsigned*>(p + 16);
                    b10[nt] = *reinterpret_cast<const unsigned*>(p + 32);
                    b11[nt] = *reinterpret_cast<const unsigned*>(p + 48);
                }
#pragma unroll
                for (int nt = 0; nt < 2; ++nt) {
                    IMMA16832(dh[0][nt], ah0[0], b00[nt], b01[nt]);
                    IMMA16832(dh[1][nt], ah0[1], b00[nt], b01[nt]);
                    IMMA16832(dh[0][nt], ah1[0], b10[nt], b11[nt]);
                    IMMA16832(dh[1][nt], ah1[1], b10[nt], b11[nt]);
                }
            }
        };
        auto alu_phase = [&]() {
#pragma unroll 1
            for (int koff = 0; koff < 7; ++koff) {
                const char* rowb = rowb_b + koff * SPT_PITCH;
                const uint4* a4p = a4base + koff * 256;
#pragma unroll
                for (int qr = 0; qr < 4; ++qr) {
                    const int off = qr * 16;
                    uint4 r0v = *reinterpret_cast<const uint4*>(rowb + off);
                    uint4 r1v = *reinterpret_cast<const uint4*>(rowb + SPT_PITCH + off);
                    uint4 r8v = *reinterpret_cast<const uint4*>(rowb + 8 * SPT_PITCH + off);
                    uint4 r9v = *reinterpret_cast<const uint4*>(rowb + 9 * SPT_PITCH + off);
                    unsigned w0[4] = {r0v.x, r0v.y, r0v.z, r0v.w};
                    unsigned w1v[4] = {r1v.x, r1v.y, r1v.z, r1v.w};
                    unsigned w8[4] = {r8v.x, r8v.y, r8v.z, r8v.w};
                    unsigned w9[4] = {r9v.x, r9v.y, r9v.z, r9v.w};
#pragma unroll
                    for (int cw = 0; cw < 4; ++cw) {
                        const int c1w = qr * 4 + cw;
                        uint4 a4 = a4p[c1w * 16];
                        unsigned bw00 = w0[cw], bw01 = w1v[cw];
                        unsigned bw10 = w8[cw], bw11 = w9[cw];
                        dp4a(ds[0][0][0], a4.x, bw00); dp4a(ds[0][0][1], a4.x, bw01);
                        dp4a(ds[0][0][2], a4.y, bw00); dp4a(ds[0][0][3], a4.y, bw01);
                        dp4a(ds[0][1][0], a4.x, bw10); dp4a(ds[0][1][1], a4.x, bw11);
                        dp4a(ds[0][1][2], a4.y, bw10); dp4a(ds[0][1][3], a4.y, bw11);
                        dp4a(ds[1][0][0], a4.z, bw00); dp4a(ds[1][0][1], a4.z, bw01);
                        dp4a(ds[1][0][2], a4.w, bw00); dp4a(ds[1][0][3], a4.w, bw01);
                        dp4a(ds[1][1][0], a4.z, bw10); dp4a(ds[1][1][1], a4.z, bw11);
                        dp4a(ds[1][1][2], a4.w, bw10); dp4a(ds[1][1][3], a4.w, bw11);
                    }
                }
            }
        };

        // ---- block-parity anti-phase ----
        if (swapord) { alu_phase(); tensor_phase(); }
        else         { tensor_phase(); alu_phase(); }

        // ---- LIF2: q = ds(lo, dp4a) + (dh(hi, IMMA) << 8), exact integer ----
#pragma unroll
        for (int mt = 0; mt < 2; ++mt)
#pragma unroll
            for (int nt = 0; nt < 2; ++nt)
#pragma unroll
                for (int e = 0; e < 4; ++e) {
                    int hf = e >> 1;
                    int q = ds[mt][nt][e] + (dh[mt][nt][e] << 8);
                    float hval = fmaf((float)q, SCALE, bb[mt][hf]);
                    float vv = v[mt][nt][e];
                    vv = fmaf(hval - vv, INV_TAU, vv);
                    if (vv >= 0.5f) { accs[mt][hf] += 1.f; vv = 0.f; }
                    v[mt][nt][e] = vv;
                }

        __syncthreads();
    }

#pragma unroll
    for (int mt = 0; mt < 2; ++mt)
#pragma unroll
        for (int hf = 0; hf < 2; ++hf) {
            int c2 = c2h * 64 + wy * 32 + mt * 16 + g + hf * 8;
            atomicAdd(&g_pool[b * C2_ + c2], accs[mt][hf]);
        }
}

// ============================================================================
// Kernel E: FC
// ============================================================================
__global__ void fc_kernel(const float* __restrict__ fcw,
                          const float* __restrict__ fcb,
                          float* __restrict__ out) {
    const int tid = threadIdx.x;
    if (tid < B_ * 4) {
        int b = tid >> 2, n = tid & 3;
        float s = 0.f;
#pragma unroll 8
        for (int c = 0; c < C2_; ++c)
            s += g_pool[b * C2_ + c] * fcw[n * C2_ + c];
        out[b * 4 + n] = s * (1.f / (float)(TT_ * LEN_)) + fcb[n];
    }
}

// ============================================================================
extern "C" void kernel_launch(void* const* d_in, const int* in_sizes, int n_in,
                              void* d_out, int out_size) {
    const float* x   = (const float*)d_in[0];
    const float* w1  = (const float*)d_in[1];
    const float* b1  = (const float*)d_in[2];
    const float* w2  = (const float*)d_in[3];
    const float* b2  = (const float*)d_in[4];
    const float* fcw = (const float*)d_in[5];
    const float* fcb = (const float*)d_in[6];
    float* out = (float*)d_out;

    cudaFuncSetAttribute(conv2f_kernel,
                         cudaFuncAttributeMaxDynamicSharedMemorySize, SMEM_SZ);

    w2prep_kernel<<<28, 256>>>(w2);                                             // 1
    transpose_kernel<<<dim3(TT_ / 32, LEN_ / 32, B_ * CIN_), dim3(32, 8)>>>(x); // 2
    conv1_kernel<<<dim3(LEN_ / 128, B_, TT_), 256>>>(w1, b1);                   // 3
    conv2f_kernel<<<dim3(16, 2, B_), 256, SMEM_SZ>>>(b2);                       // 4 <- ncu
    fc_kernel<<<1, 128>>>(fcw, fcb, out);                                       // 5
}

// round 17
// speedup vs baseline: 1.0918x; 1.0918x over previous
#include <cuda_runtime.h>
#include <cuda_bf16.h>
#include <cstdint>

#define B_    32
#define CIN_  12
#define LEN_  1024
#define TT_   64
#define C1_   64
#define C2_   128

// Scratch (device globals; no runtime allocation)
__device__ float         g_xT[TT_ * B_ * CIN_ * LEN_];          // [t][b][cin][l]
__device__ unsigned char g_s1T[(size_t)TT_ * B_ * LEN_ * C1_];  // [t][b][l][c1] spikes
__device__ uint4         g_Apk[7168];      // packed s8 w2 frags [c2h][plane][mi][chunk][lane]
__device__ uint4         g_Alo4[2 * 1792]; // lo plane frag-vectors [c2h][koff][c1w][wy][g]
__device__ float         g_pool[B_ * C2_];

typedef unsigned long long u64;

// ---- packed f32x2 helpers (conv1) ----
__device__ __forceinline__ u64 pack2(float lo, float hi) {
    u64 r;
    asm("mov.b64 %0, {%1, %2};" : "=l"(r) : "f"(lo), "f"(hi));
    return r;
}
__device__ __forceinline__ void unpack2(u64 v, float& lo, float& hi) {
    asm("mov.b64 {%0, %1}, %2;" : "=f"(lo), "=f"(hi) : "l"(v));
}
__device__ __forceinline__ void ffma2(u64& d, u64 a, u64 b) {
    asm("fma.rn.f32x2 %0, %1, %2, %0;" : "+l"(d) : "l"(a), "l"(b));
}
__device__ __forceinline__ void dp4a(int& acc, unsigned a, unsigned b) {
    asm("dp4a.s32.s32 %0, %1, %2, %0;" : "+r"(acc) : "r"(a), "r"(b));
}

// ---- warp MMA: m16n8k32 s8.s8.s32 ----
#define IMMA16832(D, A, B0, B1)                                              \
    asm volatile(                                                            \
        "mma.sync.aligned.m16n8k32.row.col.s32.s8.s8.s32 "                   \
        "{%0,%1,%2,%3}, {%4,%5,%6,%7}, {%8,%9}, {%0,%1,%2,%3};"              \
        : "+r"((D)[0]), "+r"((D)[1]), "+r"((D)[2]), "+r"((D)[3])             \
        : "r"((A).x), "r"((A).y), "r"((A).z), "r"((A).w), "r"(B0), "r"(B1))

// ============================================================================
// Kernel A: quantize + pack w2 (exact 2-plane split at 2^15) + zero g_pool.
// ============================================================================
__global__ void __launch_bounds__(256) w2prep_kernel(const float* __restrict__ w2) {
    int idx = blockIdx.x * 256 + threadIdx.x;
    if (idx < B_ * C2_) g_pool[idx] = 0.f;
    if (idx >= 7168) return;

    auto lo_of = [&](int m, int c1, int koff) -> int {
        float w = w2[m * 448 + c1 * 7 + koff];
        int q = __float2int_rn(w * 32768.f);
        int hi = (q + 128) >> 8;
        return q - (hi << 8);
    };

    // ---- IMMA fragment packing (hi plane used by conv2f) ----
    {
        int lane = idx & 31;
        int r    = idx >> 5;
        int chunk = r % 14;
        int r2    = r / 14;
        int mi    = r2 & 3;
        int plane = (r2 >> 2) & 1;
        int c2h   = r2 >> 3;
        int g = lane >> 2, c = lane & 3;
        int h = chunk & 1, koff = chunk >> 1;
        int m0 = c2h * 64 + mi * 16;
        int c1b = 32 * h + 4 * c;

        auto pk4 = [&](int m, int c1s) -> unsigned {
            unsigned rr = 0;
#pragma unroll
            for (int j = 0; j < 4; ++j) {
                float w = w2[m * 448 + (c1s + j) * 7 + koff];
                int q = __float2int_rn(w * 32768.f);
                int hi = (q + 128) >> 8;
                int lo = q - (hi << 8);
                int val = plane ? lo : hi;
                rr |= ((unsigned)(val & 0xFF)) << (8 * j);
            }
            return rr;
        };
        uint4 out;
        out.x = pk4(m0 + g,     c1b);
        out.y = pk4(m0 + g + 8, c1b);
        out.z = pk4(m0 + g,     c1b + 16);
        out.w = pk4(m0 + g + 8, c1b + 16);
        g_Apk[idx] = out;
    }

    // ---- dp4a lo fragment vectors (full plane, c1 0..63) ----
    if (idx < 3584) {
        int g    = idx & 7;
        int wy   = (idx >> 3) & 1;
        int c1w  = (idx >> 4) & 15;
        int kk   = idx >> 8;            // c2h*7 + koff
        int koff = kk % 7;
        int c2h  = kk / 7;
        unsigned w4[4];
#pragma unroll
        for (int j = 0; j < 4; ++j) {
            int m = c2h * 64 + wy * 32 + g + 8 * j;
            unsigned rr = 0;
#pragma unroll
            for (int jj = 0; jj < 4; ++jj) {
                int lo = lo_of(m, 4 * c1w + jj, koff);
                rr |= ((unsigned)(lo & 0xFF)) << (8 * jj);
            }
            w4[j] = rr;
        }
        g_Alo4[idx] = make_uint4(w4[0], w4[1], w4[2], w4[3]);
    }
}

// ============================================================================
// Kernel B: transpose x [b][cin][l][t] -> g_xT [t][b][cin][l]
// ============================================================================
__global__ void __launch_bounds__(256) transpose_kernel(const float* __restrict__ x) {
    __shared__ float tile[32][33];
    const int bc = blockIdx.z;
    const int t0 = blockIdx.x * 32;
    const int l0 = blockIdx.y * 32;
    const int tx = threadIdx.x;
    const int ty = threadIdx.y;
    const float* xb = x + (size_t)bc * LEN_ * TT_;
#pragma unroll
    for (int j = 0; j < 4; ++j)
        tile[ty + j * 8][tx] = xb[(size_t)(l0 + ty + j * 8) * TT_ + t0 + tx];
    __syncthreads();
#pragma unroll
    for (int j = 0; j < 4; ++j)
        g_xT[((size_t)(t0 + ty + j * 8) * (B_ * CIN_) + bc) * LEN_ + l0 + tx] =
            tile[tx][ty + j * 8];
}

// ============================================================================
// Kernel C: conv1 (12->64, K=7) + LIF1 (tau=1 stateless), FFMA2, standalone.
// Emits spikes TRANSPOSED: g_s1T[t][b][l][c1] via smem tile.
// ============================================================================
__global__ void __launch_bounds__(256) conv1_kernel(const float* __restrict__ w1,
                                                    const float* __restrict__ b1) {
    __shared__ float ws[84 * 68];
    __shared__ float xs[12][136];
    __shared__ unsigned char st[128 * 80];   // [l_local][c1], pitch 80

    const int tid = threadIdx.x;
    const int l0  = blockIdx.x * 128;
    const int b   = blockIdx.y;
    const int t   = blockIdx.z;

    for (int i = tid; i < C1_ * 84; i += 256) {
        int c1 = i / 84, r = i % 84;
        ws[r * 68 + c1] = w1[i];
    }
    const float* xb = g_xT + ((size_t)(t * B_ + b) * CIN_) * LEN_;
    for (int i = tid; i < 12 * 134; i += 256) {
        int cin = i / 134, j = i % 134;
        int l = l0 - 3 + j;
        xs[cin][j] = (l >= 0 && l < LEN_) ? xb[cin * LEN_ + l] : 0.f;
    }
    __syncthreads();

    const int c1g = tid >> 5;
    const int lg  = tid & 31;

    u64 acc[8][2];
#pragma unroll
    for (int c = 0; c < 8; ++c) { acc[c][0] = 0ull; acc[c][1] = 0ull; }

#pragma unroll 1
    for (int cin = 0; cin < 12; ++cin) {
        const float* sp = &xs[cin][lg * 4];
        float4 a0 = *reinterpret_cast<const float4*>(sp);
        float4 a1 = *reinterpret_cast<const float4*>(sp + 4);
        float4 a2 = *reinterpret_cast<const float4*>(sp + 8);
        float sv[12] = {a0.x, a0.y, a0.z, a0.w, a1.x, a1.y, a1.z, a1.w,
                        a2.x, a2.y, a2.z, a2.w};
        u64 pv[9];
#pragma unroll
        for (int j = 0; j < 9; ++j) pv[j] = pack2(sv[j], sv[j + 1]);
#pragma unroll
        for (int k = 0; k < 7; ++k) {
            const float* wp = &ws[(cin * 7 + k) * 68 + c1g * 8];
            float4 w0 = *reinterpret_cast<const float4*>(wp);
            float4 w1v = *reinterpret_cast<const float4*>(wp + 4);
            float wr[8] = {w0.x, w0.y, w0.z, w0.w, w1v.x, w1v.y, w1v.z, w1v.w};
#pragma unroll
            for (int c = 0; c < 8; ++c) {
                u64 wb = pack2(wr[c], wr[c]);
                ffma2(acc[c][0], pv[k], wb);
                ffma2(acc[c][1], pv[k + 2], wb);
            }
        }
    }

    // spikes for 8 c1 x 4 l -> byte matrix, write rows into st
    unsigned char sp8[4][8];
#pragma unroll
    for (int c = 0; c < 8; ++c) {
        float bb = b1[c1g * 8 + c];
        float v0, v1, v2, v3;
        unpack2(acc[c][0], v0, v1);
        unpack2(acc[c][1], v2, v3);
        sp8[0][c] = (2.f * (v0 + bb) >= 0.5f) ? 1 : 0;
        sp8[1][c] = (2.f * (v1 + bb) >= 0.5f) ? 1 : 0;
        sp8[2][c] = (2.f * (v2 + bb) >= 0.5f) ? 1 : 0;
        sp8[3][c] = (2.f * (v3 + bb) >= 0.5f) ? 1 : 0;
    }
#pragma unroll
    for (int i = 0; i < 4; ++i) {
        u64 v = 0;
#pragma unroll
        for (int c = 0; c < 8; ++c) v |= (u64)sp8[i][c] << (8 * c);
        *reinterpret_cast<u64*>(st + (lg * 4 + i) * 80 + c1g * 8) = v;
    }
    __syncthreads();

    // coalesced write-out: 128 rows x 64 B
    unsigned char* dst = g_s1T + ((size_t)(t * B_ + b) * LEN_ + l0) * 64;
#pragma unroll
    for (int j = 0; j < 2; ++j) {
        int idx = tid * 2 + j;
        int row = idx >> 2, q = idx & 3;
        uint4 val = *reinterpret_cast<const uint4*>(st + row * 80 + q * 16);
        *reinterpret_cast<uint4*>(dst + row * 64 + q * 16) = val;
    }
}

// ============================================================================
// Kernel D: slim conv2 (r15 structure) at 3 BLOCKS/SM: 206.6 KB smem total,
// 84-reg cap. Only recurring global traffic is streaming spike LDGs, so the
// shrunken L1 (21 KB) is harmless (r13's failure mode was __ldg'd weights).
// ============================================================================
#define SPT_PITCH 80
#define SPT_ROWS  70
#define OFF_SA   0                       //  28672 B  IMMA A frags (hi plane)
#define OFF_ALO  28672                   //  28672 B  dp4a lo frag vectors
#define OFF_SPT0 (OFF_ALO + 28672)       //   5760 B
#define OFF_SPT1 (OFF_SPT0 + 5760)       //   5760 B
#define SMEM_SZ  (OFF_SPT1 + 5760)       //  68864 B

extern __shared__ char fsm[];

__global__ void __launch_bounds__(256, 3)
conv2f_kernel(const float* __restrict__ b2) {
    const int tid  = threadIdx.x;
    const int lane = tid & 31;
    const int wid  = tid >> 5;
    const int wy = wid >> 2;        // 0..1  M group of 32
    const int wx = wid & 3;         // 0..3  N group of 16
    const int g  = lane >> 2;
    const int c  = lane & 3;
    const int lt  = blockIdx.x;     // 0..15
    const int c2h = blockIdx.y;     // 0..1
    const int b   = blockIdx.z;     // 0..31
    const int l0  = lt * 64;

    uint4* sA    = reinterpret_cast<uint4*>(fsm + OFF_SA);
    uint4* sAlo4 = reinterpret_cast<uint4*>(fsm + OFF_ALO);
    char*  spt[2] = {fsm + OFF_SPT0, fsm + OFF_SPT1};

    // ---- one-time staging ----
    {
#pragma unroll 7
        for (int i = tid; i < 1792; i += 256) {
            int mi = i / 448, rem = i % 448;
            sA[i] = g_Apk[(c2h * 8 + mi) * 448 + rem];
        }
        const uint4* gL = g_Alo4 + c2h * 1792;
#pragma unroll 7
        for (int i = tid; i < 1792; i += 256) sAlo4[i] = gL[i];
    }

    // per-t spike tile copy (70 rows x 64 B)
    auto construct = [&](int t, char* buf) {
        const uint4* gs = reinterpret_cast<const uint4*>(
            g_s1T + ((size_t)(t * B_ + b) * LEN_) * 64);
#pragma unroll 2
        for (int i = tid; i < SPT_ROWS * 4; i += 256) {
            int j = i >> 2, q = i & 3;
            int l = l0 - 3 + j;
            uint4 val = make_uint4(0, 0, 0, 0);
            if (l >= 0 && l < LEN_) val = gs[l * 4 + q];
            *reinterpret_cast<uint4*>(buf + j * SPT_PITCH + q * 16) = val;
        }
    };

    construct(0, spt[0]);
    __syncthreads();

    float bb[2][2];
#pragma unroll
    for (int mt = 0; mt < 2; ++mt)
#pragma unroll
        for (int hf = 0; hf < 2; ++hf)
            bb[mt][hf] = 2.f * b2[c2h * 64 + wy * 32 + mt * 16 + g + hf * 8];

    float v[2][2][4];
#pragma unroll
    for (int mt = 0; mt < 2; ++mt)
#pragma unroll
        for (int nt = 0; nt < 2; ++nt)
#pragma unroll
            for (int e = 0; e < 4; ++e) v[mt][nt][e] = 0.f;
    float accs[2][2] = {{0.f, 0.f}, {0.f, 0.f}};

    const float SCALE = 6.103515625e-05f;   // 2^-14
    const float INV_TAU = 1.0f / 0.9f;

    // hoisted invariant bases (per-thread constants)
    const uint4* sA_l    = sA + lane;
    const uint4* a4base  = sAlo4 + wy * 8 + g;
    const int    browOff = (wx * 16 + g) * SPT_PITCH + c * 4;
    const int    rowbOff = (wx * 16 + 2 * c) * SPT_PITCH;

#pragma unroll 1
    for (int t = 0; t < TT_; ++t) {
        const char* curB = spt[t & 1];

        // issue next tile's loads first: LDG latency hides under compute
        if (t + 1 < TT_) construct(t + 1, spt[(t + 1) & 1]);

        const char* brow_b = curB + browOff;
        const char* rowb_b = curB + rowbOff;

        int dh[2][2][4], ds[2][2][4];
#pragma unroll
        for (int mt = 0; mt < 2; ++mt)
#pragma unroll
            for (int nt = 0; nt < 2; ++nt)
#pragma unroll
                for (int e = 0; e < 4; ++e) { dh[mt][nt][e] = 0; ds[mt][nt][e] = 0; }

        // ==== koff loop: tensor (hi, IMMA) + alu (lo, dp4a) interleaved ====
#pragma unroll 1
        for (int koff = 0; koff < 7; ++koff) {
            // ---- tensor: 8 IMMAs (hi plane, h0 + h1) ----
            const int ch0 = koff * 2, ch1 = ch0 + 1;
            uint4 ah0[2], ah1[2];
#pragma unroll
            for (int mt = 0; mt < 2; ++mt) {
                int mi = wy * 2 + mt;
                ah0[mt] = sA_l[(mi * 14 + ch0) * 32];
                ah1[mt] = sA_l[(mi * 14 + ch1) * 32];
            }
            const char* brow = brow_b + koff * SPT_PITCH;
            unsigned b00[2], b01[2], b10[2], b11[2];
#pragma unroll
            for (int nt = 0; nt < 2; ++nt) {
                const char* p = brow + nt * 8 * SPT_PITCH;
                b00[nt] = *reinterpret_cast<const unsigned*>(p);
                b01[nt] = *reinterpret_cast<const unsigned*>(p + 16);
                b10[nt] = *reinterpret_cast<const unsigned*>(p + 32);
                b11[nt] = *reinterpret_cast<const unsigned*>(p + 48);
            }
#pragma unroll
            for (int nt = 0; nt < 2; ++nt) {
                IMMA16832(dh[0][nt], ah0[0], b00[nt], b01[nt]);
                IMMA16832(dh[1][nt], ah0[1], b00[nt], b01[nt]);
                IMMA16832(dh[0][nt], ah1[0], b10[nt], b11[nt]);
                IMMA16832(dh[1][nt], ah1[1], b10[nt], b11[nt]);
            }

            // ---- alu: dp4a FULL lo plane, 4 quarters of 4 c1w ----
            {
                const char* rowb = rowb_b + koff * SPT_PITCH;
                const uint4* a4p = a4base + koff * 256;
#pragma unroll
                for (int qr = 0; qr < 4; ++qr) {
                    const int off = qr * 16;
                    uint4 r0v = *reinterpret_cast<const uint4*>(rowb + off);
                    uint4 r1v = *reinterpret_cast<const uint4*>(rowb + SPT_PITCH + off);
                    uint4 r8v = *reinterpret_cast<const uint4*>(rowb + 8 * SPT_PITCH + off);
                    uint4 r9v = *reinterpret_cast<const uint4*>(rowb + 9 * SPT_PITCH + off);
                    unsigned w0[4] = {r0v.x, r0v.y, r0v.z, r0v.w};
                    unsigned w1v[4] = {r1v.x, r1v.y, r1v.z, r1v.w};
                    unsigned w8[4] = {r8v.x, r8v.y, r8v.z, r8v.w};
                    unsigned w9[4] = {r9v.x, r9v.y, r9v.z, r9v.w};
#pragma unroll
                    for (int cw = 0; cw < 4; ++cw) {
                        const int c1w = qr * 4 + cw;
                        uint4 a4 = a4p[c1w * 16];
                        unsigned bw00 = w0[cw], bw01 = w1v[cw];
                        unsigned bw10 = w8[cw], bw11 = w9[cw];
                        dp4a(ds[0][0][0], a4.x, bw00); dp4a(ds[0][0][1], a4.x, bw01);
                        dp4a(ds[0][0][2], a4.y, bw00); dp4a(ds[0][0][3], a4.y, bw01);
                        dp4a(ds[0][1][0], a4.x, bw10); dp4a(ds[0][1][1], a4.x, bw11);
                        dp4a(ds[0][1][2], a4.y, bw10); dp4a(ds[0][1][3], a4.y, bw11);
                        dp4a(ds[1][0][0], a4.z, bw00); dp4a(ds[1][0][1], a4.z, bw01);
                        dp4a(ds[1][0][2], a4.w, bw00); dp4a(ds[1][0][3], a4.w, bw01);
                        dp4a(ds[1][1][0], a4.z, bw10); dp4a(ds[1][1][1], a4.z, bw11);
                        dp4a(ds[1][1][2], a4.w, bw10); dp4a(ds[1][1][3], a4.w, bw11);
                    }
                }
            }
        }

        // ---- LIF2: q = ds(lo, dp4a) + (dh(hi, IMMA) << 8), exact integer ----
#pragma unroll
        for (int mt = 0; mt < 2; ++mt)
#pragma unroll
            for (int nt = 0; nt < 2; ++nt)
#pragma unroll
                for (int e = 0; e < 4; ++e) {
                    int hf = e >> 1;
                    int q = ds[mt][nt][e] + (dh[mt][nt][e] << 8);
                    float hval = fmaf((float)q, SCALE, bb[mt][hf]);
                    float vv = v[mt][nt][e];
                    vv = fmaf(hval - vv, INV_TAU, vv);
                    if (vv >= 0.5f) { accs[mt][hf] += 1.f; vv = 0.f; }
                    v[mt][nt][e] = vv;
                }

        __syncthreads();
    }

#pragma unroll
    for (int mt = 0; mt < 2; ++mt)
#pragma unroll
        for (int hf = 0; hf < 2; ++hf) {
            int c2 = c2h * 64 + wy * 32 + mt * 16 + g + hf * 8;
            atomicAdd(&g_pool[b * C2_ + c2], accs[mt][hf]);
        }
}

// ============================================================================
// Kernel E: FC
// ============================================================================
__global__ void fc_kernel(const float* __restrict__ fcw,
                          const float* __restrict__ fcb,
                          float* __restrict__ out) {
    const int tid = threadIdx.x;
    if (tid < B_ * 4) {
        int b = tid >> 2, n = tid & 3;
        float s = 0.f;
#pragma unroll 8
        for (int c = 0; c < C2_; ++c)
            s += g_pool[b * C2_ + c] * fcw[n * C2_ + c];
        out[b * 4 + n] = s * (1.f / (float)(TT_ * LEN_)) + fcb[n];
    }
}

// ============================================================================
extern "C" void kernel_launch(void* const* d_in, const int* in_sizes, int n_in,
                              void* d_out, int out_size) {
    const float* x   = (const float*)d_in[0];
    const float* w1  = (const float*)d_in[1];
    const float* b1  = (const float*)d_in[2];
    const float* w2  = (const float*)d_in[3];
    const float* b2  = (const float*)d_in[4];
    const float* fcw = (const float*)d_in[5];
    const float* fcb = (const float*)d_in[6];
    float* out = (float*)d_out;

    cudaFuncSetAttribute(conv2f_kernel,
                         cudaFuncAttributeMaxDynamicSharedMemorySize, SMEM_SZ);

    w2prep_kernel<<<28, 256>>>(w2);                                             // 1
    transpose_kernel<<<dim3(TT_ / 32, LEN_ / 32, B_ * CIN_), dim3(32, 8)>>>(x); // 2
    conv1_kernel<<<dim3(LEN_ / 128, B_, TT_), 256>>>(w1, b1);                   // 3
    conv2f_kernel<<<dim3(16, 2, B_), 256, SMEM_SZ>>>(b2);                       // 4 <- ncu
    fc_kernel<<<1, 128>>>(fcw, fcb, out);                                       // 5
}